// round 17
// baseline (speedup 1.0000x reference)
#include <cuda_runtime.h>
#include <cuda_bf16.h>
#include <math.h>
#include <stdint.h>

#define BB 8
#define QQ 2048
#define SS 2048
#define DD 512
#define EE 512

#define BKC 32
#define ROWB 80
#define NSTAGE 3
#define SMEM_SZ (NSTAGE * 2 * (128 + 256) * ROWB)   // 184320

typedef __nv_bfloat16 bf16;

// hi/lo split operands (device-global scratch)
__device__ bf16 g_qh[(size_t)BB * QQ * DD], g_ql[(size_t)BB * QQ * DD];
__device__ bf16 g_wth[(size_t)EE * DD],     g_wtl[(size_t)EE * DD];
__device__ bf16 g_vh[(size_t)BB * SS * EE], g_vl[(size_t)BB * SS * EE];
__device__ bf16 g_vth[(size_t)BB * EE * SS], g_vtl[(size_t)BB * EE * SS];
__device__ bf16 g_tqh[(size_t)BB * QQ * EE], g_tql[(size_t)BB * QQ * EE];
__device__ bf16 g_ah[(size_t)BB * QQ * SS], g_al[(size_t)BB * QQ * SS];

__device__ __forceinline__ uint32_t s2u(const void* p) {
    uint32_t a;
    asm("{ .reg .u64 t; cvta.to.shared.u64 t, %1; cvt.u32.u64 %0, t; }" : "=r"(a) : "l"(p));
    return a;
}
__device__ __forceinline__ void split1(float v, bf16& h, bf16& l) {
    h = __float2bfloat16(v);
    l = __float2bfloat16(v - __bfloat162float(h));
}
__device__ __forceinline__ void cp16(uint32_t sa, const void* ga) {
    asm volatile("cp.async.cg.shared.global [%0], [%1], 16;" :: "r"(sa), "l"(ga) : "memory");
}
#define CP_COMMIT() asm volatile("cp.async.commit_group;" ::: "memory")
#define CP_WAIT(n)  asm volatile("cp.async.wait_group %0;" :: "n"(n) : "memory")
#define LDSM4(r, addr) \
    asm volatile("ldmatrix.sync.aligned.m8n8.x4.shared.b16 {%0,%1,%2,%3}, [%4];" \
        : "=r"((r)[0]), "=r"((r)[1]), "=r"((r)[2]), "=r"((r)[3]) : "r"(addr))
#define MMA16816(d, a, b) \
    asm volatile("mma.sync.aligned.m16n8k16.row.col.f32.bf16.bf16.f32 " \
        "{%0,%1,%2,%3}, {%4,%5,%6,%7}, {%8,%9}, {%0,%1,%2,%3};" \
        : "+f"((d)[0]), "+f"((d)[1]), "+f"((d)[2]), "+f"((d)[3]) \
        : "r"((a)[0]), "r"((a)[1]), "r"((a)[2]), "r"((a)[3]), "r"((b)[0]), "r"((b)[1]))

// ---------------------------------------------------------------------------
// query fp32 -> hi/lo bf16 (same layout). x0: block offset for stream split.
// ---------------------------------------------------------------------------
__global__ __launch_bounds__(256)
void conv_query(const float* __restrict__ src, int x0)
{
    size_t i = ((size_t)(blockIdx.x + x0) * 256 + threadIdx.x) * 4;
    float4 v = __ldg((const float4*)(src + i));
    bf16 h0, h1, h2, h3, l0, l1, l2, l3;
    split1(v.x, h0, l0); split1(v.y, h1, l1);
    split1(v.z, h2, l2); split1(v.w, h3, l3);
    __nv_bfloat162* ph = (__nv_bfloat162*)(g_qh + i);
    __nv_bfloat162* pl = (__nv_bfloat162*)(g_ql + i);
    ph[0] = __nv_bfloat162(h0, h1); ph[1] = __nv_bfloat162(h2, h3);
    pl[0] = __nv_bfloat162(l0, l1); pl[1] = __nv_bfloat162(l2, l3);
}

// ---------------------------------------------------------------------------
// W fp32 [D][E] -> transposed hi/lo bf16 [E][D].
// ---------------------------------------------------------------------------
__global__ __launch_bounds__(256)
void trans_w(const float* __restrict__ src)
{
    __shared__ float t[32][33];
    const int r0 = blockIdx.y * 32, c0 = blockIdx.x * 32;
    const int tx = threadIdx.x & 31, ty = threadIdx.x >> 5;
    #pragma unroll
    for (int i = ty; i < 32; i += 8)
        t[i][tx] = src[(long)(r0 + i) * EE + c0 + tx];
    __syncthreads();
    const int a = threadIdx.x & 15, iy = threadIdx.x >> 4;
    #pragma unroll
    for (int p = 0; p < 2; ++p) {
        int i = iy + p * 16;
        float v0 = t[2 * a][i], v1 = t[2 * a + 1][i];
        bf16 h0, h1, l0, l1;
        split1(v0, h0, l0); split1(v1, h1, l1);
        long o = (long)(c0 + i) * DD + r0 + 2 * a;
        *(__nv_bfloat162*)(g_wth + o) = __nv_bfloat162(h0, h1);
        *(__nv_bfloat162*)(g_wtl + o) = __nv_bfloat162(l0, l1);
    }
}

// ---------------------------------------------------------------------------
// values fp32 [B][S][E]: one read -> g_vh/g_vl AND g_vth/g_vtl (transposed).
// ---------------------------------------------------------------------------
__global__ __launch_bounds__(256)
void prep_values(const float* __restrict__ src)
{
    __shared__ float t[32][33];
    const long zb = (long)blockIdx.z;
    src   += zb * SS * EE;
    bf16* vh  = g_vh  + zb * SS * EE;
    bf16* vl  = g_vl  + zb * SS * EE;
    bf16* vth = g_vth + zb * EE * SS;
    bf16* vtl = g_vtl + zb * EE * SS;
    const int r0 = blockIdx.y * 32, c0 = blockIdx.x * 32;
    const int tx = threadIdx.x & 31, ty = threadIdx.x >> 5;
    #pragma unroll
    for (int i = ty; i < 32; i += 8)
        t[i][tx] = src[(long)(r0 + i) * EE + c0 + tx];
    __syncthreads();
    const int a = threadIdx.x & 15, iy = threadIdx.x >> 4;
    #pragma unroll
    for (int p = 0; p < 2; ++p) {
        int i = iy + p * 16;
        {
            float v0 = t[i][2 * a], v1 = t[i][2 * a + 1];
            bf16 h0, h1, l0, l1;
            split1(v0, h0, l0); split1(v1, h1, l1);
            long o = (long)(r0 + i) * EE + c0 + 2 * a;
            *(__nv_bfloat162*)(vh + o) = __nv_bfloat162(h0, h1);
            *(__nv_bfloat162*)(vl + o) = __nv_bfloat162(l0, l1);
        }
        {
            float v0 = t[2 * a][i], v1 = t[2 * a + 1][i];
            bf16 h0, h1, l0, l1;
            split1(v0, h0, l0); split1(v1, h1, l1);
            long o = (long)(c0 + i) * SS + r0 + 2 * a;
            *(__nv_bfloat162*)(vth + o) = __nv_bfloat162(h0, h1);
            *(__nv_bfloat162*)(vtl + o) = __nv_bfloat162(l0, l1);
        }
    }
}

// ---------------------------------------------------------------------------
// NT GEMM on pre-split bf16 hi/lo operands, 3-stage cp.async, 1 sync/chunk.
// Fragment schedule: A loaded fully per k-step; B pairs rotated just-in-time
// (np+1 loaded under np's 24 MMAs). cp.async issued after first frag loads.
// ASEL: 0=query, 1=tq, 2=attn.  BSEL: 0=wt, 1=values, 2=vt.
// EPI: 0=fp32, 1=fp32+mask, 2=split hi/lo to g_tqh/g_tql.
// z0 / y0: batch / M-tile offsets for the stream split.
// ---------------------------------------------------------------------------
template <int ASEL, int BSEL, int EPI, int CM, int CN>
__global__ __launch_bounds__(256, 1)
void mma_gemm(const int* __restrict__ maskg, float* __restrict__ Cg,
              int K, int ldc, long sA, long sB, long sC, int z0, int y0)
{
    constexpr int OFF_AH = 0;
    constexpr int OFF_AL = CM * ROWB;
    constexpr int OFF_BH = 2 * CM * ROWB;
    constexpr int OFF_BL = OFF_BH + CN * ROWB;
    constexpr int STAGEB = 2 * (CM + CN) * ROWB;
    constexpr int WM = CM / 64;
    extern __shared__ char smem[];
    const uint32_t sb = s2u(smem);
    const int tid = threadIdx.x, w = tid >> 5, lane = tid & 31;
    const int bz = blockIdx.z + z0;
    const bf16* Ah = ((ASEL == 0) ? g_qh : (ASEL == 1) ? g_tqh : g_ah) + (size_t)bz * sA;
    const bf16* Al = ((ASEL == 0) ? g_ql : (ASEL == 1) ? g_tql : g_al) + (size_t)bz * sA;
    const bf16* Bh = ((BSEL == 0) ? g_wth : (BSEL == 1) ? g_vh : g_vth) + (size_t)bz * sB;
    const bf16* Bl = ((BSEL == 0) ? g_wtl : (BSEL == 1) ? g_vl : g_vtl) + (size_t)bz * sB;
    float* C = Cg + (long)bz * sC;
    const int bm = (blockIdx.y + y0) * CM, bn = blockIdx.x * CN;
    const int m0 = (w % WM) * 64, n0 = (w / WM) * 64;

    float d[4][8][4] = {};

    auto load_stage = [&](uint32_t st, int kc) {
        uint32_t so = sb + st * STAGEB;
        #pragma unroll
        for (int j = 0; j < CM * 8 / 256; ++j) {
            int idx = tid + 256 * j;
            int half = idx / (CM * 4);
            int rem = idx - half * (CM * 4);
            int row = rem >> 2, q = rem & 3;
            const bf16* g = (half ? Al : Ah) + (size_t)(bm + row) * K + kc + q * 8;
            cp16(so + (half ? OFF_AL : OFF_AH) + row * ROWB + q * 16, g);
        }
        #pragma unroll
        for (int j = 0; j < CN * 8 / 256; ++j) {
            int idx = tid + 256 * j;
            int half = idx / (CN * 4);
            int rem = idx - half * (CN * 4);
            int row = rem >> 2, q = rem & 3;
            const bf16* g = (half ? Bl : Bh) + (size_t)(bn + row) * K + kc + q * 8;
            cp16(so + (half ? OFF_BL : OFF_BH) + row * ROWB + q * 16, g);
        }
    };

    load_stage(0, 0);
    CP_COMMIT();
    load_stage(1, BKC);
    CP_COMMIT();

    const int NC = K / BKC;
    for (int c = 0; c < NC; ++c) {
        CP_WAIT(1);
        __syncthreads();
        const uint32_t stage = sb + (uint32_t)((c % NSTAGE) * STAGEB);
        #pragma unroll
        for (int ks = 0; ks < 2; ++ks) {
            const uint32_t akoff = ks * 32 + (lane >> 4) * 16;
            const uint32_t bkoff = ks * 32 + ((lane >> 3) & 1) * 16;
            // A: all m-tiles for this k-step
            uint32_t ah[4][4], al[4][4];
            #pragma unroll
            for (int mt = 0; mt < 4; ++mt) {
                uint32_t ro = (uint32_t)((m0 + mt * 16 + (lane & 15)) * ROWB);
                LDSM4(ah[mt], stage + OFF_AH + ro + akoff);
                LDSM4(al[mt], stage + OFF_AL + ro + akoff);
            }
            // B: 2-slot rotation over np blocks (each covers nt=2np,2np+1)
            uint32_t bh[2][4], bl[2][4];
            {
                uint32_t ro = (uint32_t)((n0 + ((lane >> 4) << 3) + (lane & 7)) * ROWB);
                LDSM4(bh[0], stage + OFF_BH + ro + bkoff);
                LDSM4(bl[0], stage + OFF_BL + ro + bkoff);
            }
            // issue next chunk's cp.async AFTER the first fragments are in flight
            if (ks == 0) {
                if (c + 2 < NC)
                    load_stage((c + 2) % NSTAGE, (c + 2) * BKC);
                CP_COMMIT();
            }
            #pragma unroll
            for (int np = 0; np < 4; ++np) {
                if (np < 3) {
                    uint32_t ro = (uint32_t)((n0 + (np + 1) * 16 + ((lane >> 4) << 3) + (lane & 7)) * ROWB);
                    LDSM4(bh[(np + 1) & 1], stage + OFF_BH + ro + bkoff);
                    LDSM4(bl[(np + 1) & 1], stage + OFF_BL + ro + bkoff);
                }
                #pragma unroll
                for (int j = 0; j < 2; ++j) {
                    const int nt = 2 * np + j;
                    #pragma unroll
                    for (int mt = 0; mt < 4; ++mt) {
                        MMA16816(d[mt][nt], ah[mt], &bh[np & 1][2 * j]);
                        MMA16816(d[mt][nt], ah[mt], &bl[np & 1][2 * j]);
                        MMA16816(d[mt][nt], al[mt], &bh[np & 1][2 * j]);
                    }
                }
            }
        }
    }

    const int* mrow = (EPI == 1) ? (maskg + (long)bz * ldc) : (const int*)0;
    #pragma unroll
    for (int mt = 0; mt < 4; ++mt) {
        #pragma unroll
        for (int nt = 0; nt < 8; ++nt) {
            int r0 = bm + m0 + mt * 16 + (lane >> 2);
            int col = bn + n0 + nt * 8 + (lane & 3) * 2;
            float v0 = d[mt][nt][0], v1 = d[mt][nt][1];
            float v2 = d[mt][nt][2], v3 = d[mt][nt][3];
            if (EPI == 1) {
                int k0 = __ldg(mrow + col), k1 = __ldg(mrow + col + 1);
                if (!k0) { v0 = -INFINITY; v2 = -INFINITY; }
                if (!k1) { v1 = -INFINITY; v3 = -INFINITY; }
            }
            if (EPI == 2) {
                size_t o0 = (size_t)r0 * ldc + col, o1 = (size_t)(r0 + 8) * ldc + col;
                bf16 h0, h1, h2, h3, l0, l1, l2, l3;
                split1(v0, h0, l0); split1(v1, h1, l1);
                split1(v2, h2, l2); split1(v3, h3, l3);
                *(__nv_bfloat162*)(g_tqh + o0) = __nv_bfloat162(h0, h1);
                *(__nv_bfloat162*)(g_tql + o0) = __nv_bfloat162(l0, l1);
                *(__nv_bfloat162*)(g_tqh + o1) = __nv_bfloat162(h2, h3);
                *(__nv_bfloat162*)(g_tql + o1) = __nv_bfloat162(l2, l3);
            } else {
                *(float2*)(C + (long)r0 * ldc + col)       = make_float2(v0, v1);
                *(float2*)(C + (long)(r0 + 8) * ldc + col) = make_float2(v2, v3);
            }
        }
    }
}

// ---------------------------------------------------------------------------
// In-place row softmax; emits hi/lo bf16 copy for G3. row0: stream offset.
// ---------------------------------------------------------------------------
__global__ __launch_bounds__(256)
void softmax_rows(float* __restrict__ attn, long row0)
{
    __shared__ float sm[32];
    const long row = row0 + blockIdx.x;
    float4* p = (float4*)(attn + row * (long)SS);
    const int t = threadIdx.x, lane = t & 31, wid = t >> 5;
    float4 v0 = p[t], v1 = p[t + 256];
    float m = fmaxf(fmaxf(fmaxf(v0.x, v0.y), fmaxf(v0.z, v0.w)),
                    fmaxf(fmaxf(v1.x, v1.y), fmaxf(v1.z, v1.w)));
    #pragma unroll
    for (int o = 16; o; o >>= 1) m = fmaxf(m, __shfl_xor_sync(0xffffffffu, m, o));
    if (lane == 0) sm[wid] = m;
    __syncthreads();
    if (t == 0) {
        float x = sm[0];
        #pragma unroll
        for (int i = 1; i < 8; ++i) x = fmaxf(x, sm[i]);
        sm[8] = x;
    }
    __syncthreads();
    const float rm = sm[8];
    v0.x = expf(v0.x - rm); v0.y = expf(v0.y - rm);
    v0.z = expf(v0.z - rm); v0.w = expf(v0.w - rm);
    v1.x = expf(v1.x - rm); v1.y = expf(v1.y - rm);
    v1.z = expf(v1.z - rm); v1.w = expf(v1.w - rm);
    float s = (v0.x + v0.y + v0.z + v0.w) + (v1.x + v1.y + v1.z + v1.w);
    #pragma unroll
    for (int o = 16; o; o >>= 1) s += __shfl_xor_sync(0xffffffffu, s, o);
    if (lane == 0) sm[16 + wid] = s;
    __syncthreads();
    if (t == 0) {
        float x = 0.0f;
        #pragma unroll
        for (int i = 0; i < 8; ++i) x += sm[16 + i];
        sm[24] = x;
    }
    __syncthreads();
    const float inv = 1.0f / sm[24];
    v0.x *= inv; v0.y *= inv; v0.z *= inv; v0.w *= inv;
    v1.x *= inv; v1.y *= inv; v1.z *= inv; v1.w *= inv;
    p[t] = v0; p[t + 256] = v1;

    const size_t base = (size_t)row * SS;
    float vv[8] = {v0.x, v0.y, v0.z, v0.w, v1.x, v1.y, v1.z, v1.w};
    size_t off[2] = {base + (size_t)t * 4, base + (size_t)(t + 256) * 4};
    #pragma unroll
    for (int g = 0; g < 2; ++g) {
        bf16 h0, h1, h2, h3, l0, l1, l2, l3;
        split1(vv[g*4+0], h0, l0); split1(vv[g*4+1], h1, l1);
        split1(vv[g*4+2], h2, l2); split1(vv[g*4+3], h3, l3);
        __nv_bfloat162* ph = (__nv_bfloat162*)(g_ah + off[g]);
        __nv_bfloat162* pl = (__nv_bfloat162*)(g_al + off[g]);
        ph[0] = __nv_bfloat162(h0, h1); ph[1] = __nv_bfloat162(h2, h3);
        pl[0] = __nv_bfloat162(l0, l1); pl[1] = __nv_bfloat162(l2, l3);
    }
}

extern "C" void kernel_launch(void* const* d_in, const int* in_sizes, int n_in,
                              void* d_out, int out_size)
{
    const float* query  = (const float*)d_in[0];
    const float* values = (const float*)d_in[1];
    const int*   mask   = (const int*)d_in[2];
    const float* W      = (const float*)d_in[3];

    float* context = (float*)d_out;
    float* attn    = (float*)d_out + (size_t)BB * QQ * EE;

    static cudaStream_t s2 = nullptr;
    static cudaEvent_t ev0 = nullptr, evW = nullptr, evPV = nullptr, evEnd = nullptr;
    if (!s2) {
        cudaStreamCreateWithFlags(&s2, cudaStreamNonBlocking);
        cudaEventCreateWithFlags(&ev0,  cudaEventDisableTiming);
        cudaEventCreateWithFlags(&evW,  cudaEventDisableTiming);
        cudaEventCreateWithFlags(&evPV, cudaEventDisableTiming);
        cudaEventCreateWithFlags(&evEnd, cudaEventDisableTiming);
    }

    cudaFuncSetAttribute(mma_gemm<0,0,2,256,128>, cudaFuncAttributeMaxDynamicSharedMemorySize, SMEM_SZ);
    cudaFuncSetAttribute(mma_gemm<1,1,1,128,256>, cudaFuncAttributeMaxDynamicSharedMemorySize, SMEM_SZ);
    cudaFuncSetAttribute(mma_gemm<2,2,0,256,128>, cudaFuncAttributeMaxDynamicSharedMemorySize, SMEM_SZ);

    // fork
    cudaEventRecord(ev0, 0);
    cudaStreamWaitEvent(s2, ev0, 0);

    // s0: query-lo split, W^T, G1 for batches 0-3 (rows 0..8191)
    conv_query<<<4096, 256>>>(query, 0);
    trans_w<<<dim3(EE/32, DD/32, 1), 256>>>(W);
    cudaEventRecord(evW, 0);
    mma_gemm<0,0,2,256,128><<<dim3(EE/128, 32, 1), 256, SMEM_SZ>>>(
        (const int*)0, (float*)0, DD, EE, 0L, 0L, 0L, 0, 0);

    // s2: values prep, query-hi split, G1 for batches 4-7 (needs W^T)
    prep_values<<<dim3(EE/32, SS/32, BB), 256, 0, s2>>>(values);
    cudaEventRecord(evPV, s2);
    conv_query<<<4096, 256, 0, s2>>>(query, 4096);
    cudaStreamWaitEvent(s2, evW, 0);
    mma_gemm<0,0,2,256,128><<<dim3(EE/128, 32, 1), 256, SMEM_SZ, s2>>>(
        (const int*)0, (float*)0, DD, EE, 0L, 0L, 0L, 0, 32);

    // chain A (batches 0-3) on s0 — needs prep_values from s2
    cudaStreamWaitEvent(0, evPV, 0);
    mma_gemm<1,1,1,128,256><<<dim3(SS/256, QQ/128, 4), 256, SMEM_SZ>>>(
        mask, attn, EE, SS, (long)QQ*EE, (long)SS*EE, (long)QQ*SS, 0, 0);
    softmax_rows<<<4*QQ, 256>>>(attn, 0L);
    mma_gemm<2,2,0,256,128><<<dim3(EE/128, QQ/256, 4), 256, SMEM_SZ>>>(
        (const int*)0, context, SS, EE, (long)QQ*SS, (long)EE*SS, (long)QQ*EE, 0, 0);

    // chain B (batches 4-7) on s2
    mma_gemm<1,1,1,128,256><<<dim3(SS/256, QQ/128, 4), 256, SMEM_SZ, s2>>>(
        mask, attn, EE, SS, (long)QQ*EE, (long)SS*EE, (long)QQ*SS, 4, 0);
    softmax_rows<<<4*QQ, 256, 0, s2>>>(attn, (long)4*QQ);
    mma_gemm<2,2,0,256,128><<<dim3(EE/128, QQ/256, 4), 256, SMEM_SZ, s2>>>(
        (const int*)0, context, SS, EE, (long)QQ*SS, (long)EE*SS, (long)QQ*EE, 4, 0);

    // join
    cudaEventRecord(evEnd, s2);
    cudaStreamWaitEvent(0, evEnd, 0);
}